// round 4
// baseline (speedup 1.0000x reference)
#include <cuda_runtime.h>
#include <cuda_bf16.h>
#include <math.h>

// ---------------- problem constants ----------------
#define BN     16      // batch
#define CIN    16      // input channels
#define HIN    224
#define WIN    224
#define MID    128
#define HW0    (HIN*WIN)   // 50176

typedef unsigned long long ull;

// ---------------- scratch (device globals; no allocation) ----------------
__device__ float g_act0[(size_t)BN*MID*224*224];   // conv0 raw output
__device__ float g_conv[(size_t)BN*MID*222*222];   // conv3x3 raw output (max size)
__device__ float g_pa  [(size_t)BN*MID*110*110];   // pooled ping
__device__ float g_pb  [(size_t)BN*MID*53*53];     // pooled pong
__device__ float  g_alpha[MID];
__device__ float  g_beta [MID];
__device__ float  g_feat[BN*2048];
__device__ double g_reg [BN*7];
__device__ double g_theta[BN*6];
__device__ double g_m[BN];

__device__ __forceinline__ float* getbuf(int s) {
    switch (s) {
        case 0: return g_act0;
        case 1: return g_conv;
        case 2: return g_pa;
        default: return g_pb;
    }
}

// ---------------- f32x2 packed helpers ----------------
__device__ __forceinline__ ull pk2(float lo, float hi) {
    ull r;
    asm("mov.b64 %0, {%1, %2};" : "=l"(r) : "f"(lo), "f"(hi));
    return r;
}
__device__ __forceinline__ void ffma2(ull& acc, ull a, ull b) {
    asm("fma.rn.f32x2 %0, %1, %2, %0;" : "+l"(acc) : "l"(a), "l"(b));
}
__device__ __forceinline__ void unpk2(float& lo, float& hi, ull v) {
    asm("mov.b64 {%0, %1}, %2;" : "=f"(lo), "=f"(hi) : "l"(v));
}

// ---------------- conv0: 1x1, 16 -> 128 ----------------
__global__ __launch_bounds__(256) void k_conv0(const float* __restrict__ x,
                                               const float* __restrict__ w,
                                               const float* __restrict__ b) {
    __shared__ float ws[MID*CIN];
    __shared__ float bs[MID];
    int tid = threadIdx.x;
    for (int i = tid; i < MID*CIN; i += 256) ws[i] = w[i];
    if (tid < MID) bs[tid] = b[tid];
    __syncthreads();

    long gid = (long)blockIdx.x * 256 + tid;             // pixel-group id
    int n  = (int)(gid / (HW0/4));
    int pg = (int)(gid % (HW0/4));
    int p  = pg * 4;

    const float* xp = x + (long)n*CIN*HW0 + p;
    float4 v[CIN];
    #pragma unroll
    for (int ci = 0; ci < CIN; ci++)
        v[ci] = *(const float4*)(xp + (long)ci*HW0);

    float* op = g_act0 + (long)n*MID*HW0 + p;
    for (int co = 0; co < MID; co++) {
        float4 a; a.x = a.y = a.z = a.w = bs[co];
        #pragma unroll
        for (int ci = 0; ci < CIN; ci++) {
            float wv = ws[co*CIN + ci];
            a.x = fmaf(v[ci].x, wv, a.x);
            a.y = fmaf(v[ci].y, wv, a.y);
            a.z = fmaf(v[ci].z, wv, a.z);
            a.w = fmaf(v[ci].w, wv, a.w);
        }
        *(float4*)(op + (long)co*HW0) = a;
    }
}

// ---------------- BN stats + finalize (fp64, deterministic) ----------------
__global__ void k_bn(int inbuf, int HWp, const float* __restrict__ g,
                     const float* __restrict__ b) {
    const float* p = getbuf(inbuf);
    int c = blockIdx.x;
    int tid = threadIdx.x;
    double s = 0.0, ss = 0.0;
    for (int n = 0; n < BN; n++) {
        const float* base = p + ((long)n*MID + c) * HWp;
        for (int i = tid; i < HWp; i += 256) {
            double v = (double)base[i];
            s += v; ss += v*v;
        }
    }
    __shared__ double sh[256], sh2[256];
    sh[tid] = s; sh2[tid] = ss;
    __syncthreads();
    for (int k = 128; k > 0; k >>= 1) {
        if (tid < k) { sh[tid] += sh[tid+k]; sh2[tid] += sh2[tid+k]; }
        __syncthreads();
    }
    if (tid == 0) {
        double M   = (double)BN * (double)HWp;
        double mu  = sh[0] / M;
        double var = sh2[0] / M - mu*mu;
        double a   = (double)g[c] / sqrt(var + 1e-5);
        g_alpha[c] = (float)a;
        g_beta[c]  = (float)((double)b[c] - mu*a);
    }
}

// ---------------- 3x3 valid conv, fused BN+ReLU on input ----------------
// block: 16 co x (16x16 px tile); thread: 1 co x 4x4 px
// inner math: packed f32x2 FFMA (2 output cols per instr); fp32 accumulation
// within each 8-ci chunk; fp64 fold once per chunk.
#define CI_CHUNK 8

// apply one input row (5 packed pairs) to one acc row with tap-row weights wk[3]
__device__ __forceinline__ void apply_row(ull* acc01, const ull* p, const ull* wk) {
    ffma2(acc01[0], p[0], wk[0]);
    ffma2(acc01[0], p[1], wk[1]);
    ffma2(acc01[0], p[2], wk[2]);
    ffma2(acc01[1], p[2], wk[0]);
    ffma2(acc01[1], p[3], wk[1]);
    ffma2(acc01[1], p[4], wk[2]);
}

__device__ __forceinline__ void ldpairs(ull* p, const float* base) {
    float4 v = *(const float4*)base;
    float2 w = *(const float2*)(base + 4);
    p[0] = pk2(v.x, v.y);
    p[1] = pk2(v.y, v.z);
    p[2] = pk2(v.z, v.w);
    p[3] = pk2(v.w, w.x);
    p[4] = pk2(w.x, w.y);
}

__global__ __launch_bounds__(256)
void k_conv3(int inbuf, const float* __restrict__ w, const float* __restrict__ bias,
             int HI, int WI, int HO, int WO) {
    __shared__ __align__(16) float s_in[CI_CHUNK][18][20];  // pitch 20 floats
    __shared__ __align__(16) float s_w [CI_CHUNK][16][18];  // weights duplicated {w,w}

    const float* in = getbuf(inbuf);
    float* out = g_conv;

    int tid  = threadIdx.x;
    int co   = tid >> 4;                 // 0..15
    int slot = tid & 15;                 // 0..15
    int sx   = (slot & 3) * 4;
    int sy   = (slot >> 2) * 4;
    int ox0  = blockIdx.x * 16;
    int oy0  = blockIdx.y * 16;
    int n    = blockIdx.z >> 3;
    int co0  = (blockIdx.z & 7) << 4;
    int cog  = co0 + co;

    double dacc[4][4];
    #pragma unroll
    for (int i = 0; i < 4; i++)
        #pragma unroll
        for (int j = 0; j < 4; j++) dacc[i][j] = 0.0;

    for (int ci0 = 0; ci0 < MID; ci0 += CI_CHUNK) {
        __syncthreads();
        // load + BN/ReLU-transform input tile (18x18 per ci)
        for (int idx = tid; idx < CI_CHUNK*18*18; idx += 256) {
            int ci = idx / 324;
            int r  = (idx - ci*324) / 18;
            int cc = idx - ci*324 - r*18;
            int iy = oy0 + r, ix = ox0 + cc;
            float v = 0.f;
            if (iy < HI && ix < WI)
                v = in[(((long)n*MID + ci0 + ci) * HI + iy) * WI + ix];
            v = fmaxf(fmaf(g_alpha[ci0+ci], v, g_beta[ci0+ci]), 0.f);
            s_in[ci][r][cc] = v;
        }
        // load weights, duplicated for packed math
        for (int idx = tid; idx < CI_CHUNK*16*9; idx += 256) {
            int ci  = idx / 144;
            int rem = idx - ci*144;
            int col = rem / 9, k = rem - col*9;
            float wv = w[(((long)(co0+col))*MID + ci0 + ci)*9 + k];
            s_w[ci][col][k*2]   = wv;
            s_w[ci][col][k*2+1] = wv;
        }
        __syncthreads();

        ull acc2[4][2];
        #pragma unroll
        for (int i = 0; i < 4; i++) { acc2[i][0] = 0ull; acc2[i][1] = 0ull; }

        #pragma unroll
        for (int ci = 0; ci < CI_CHUNK; ci++) {
            const ull* wq = (const ull*)&s_w[ci][co][0];   // 9 packed {w,w}
            ull wp[9];
            #pragma unroll
            for (int k = 0; k < 9; k++) wp[k] = wq[k];

            const float* base = &s_in[ci][sy][sx];
            ull p[5];
            // row r feeds acc rows i in [r-2, r], kh = r - i
            ldpairs(p, base);            // r=0
            apply_row(acc2[0], p, wp + 0);
            ldpairs(p, base + 20);       // r=1
            apply_row(acc2[0], p, wp + 3);
            apply_row(acc2[1], p, wp + 0);
            ldpairs(p, base + 40);       // r=2
            apply_row(acc2[0], p, wp + 6);
            apply_row(acc2[1], p, wp + 3);
            apply_row(acc2[2], p, wp + 0);
            ldpairs(p, base + 60);       // r=3
            apply_row(acc2[1], p, wp + 6);
            apply_row(acc2[2], p, wp + 3);
            apply_row(acc2[3], p, wp + 0);
            ldpairs(p, base + 80);       // r=4
            apply_row(acc2[2], p, wp + 6);
            apply_row(acc2[3], p, wp + 3);
            ldpairs(p, base + 100);      // r=5
            apply_row(acc2[3], p, wp + 6);
        }

        #pragma unroll
        for (int i = 0; i < 4; i++) {
            float a0, a1, a2, a3;
            unpk2(a0, a1, acc2[i][0]);
            unpk2(a2, a3, acc2[i][1]);
            dacc[i][0] += (double)a0;
            dacc[i][1] += (double)a1;
            dacc[i][2] += (double)a2;
            dacc[i][3] += (double)a3;
        }
    }

    double bv = (double)bias[cog];
    #pragma unroll
    for (int i = 0; i < 4; i++) {
        int oy = oy0 + sy + i;
        if (oy >= HO) continue;
        #pragma unroll
        for (int j = 0; j < 4; j++) {
            int ox = ox0 + sx + j;
            if (ox >= WO) continue;
            out[(((long)n*MID + cog) * HO + oy) * WO + ox] = (float)(dacc[i][j] + bv);
        }
    }
}

// ---------------- maxpool 3x3 stride 2 (valid) ----------------
__global__ void k_pool(int outbuf, int HO, int WO, int HP, int WP) {
    const float* in = g_conv;
    float* out = getbuf(outbuf);
    long idx = (long)blockIdx.x * 256 + threadIdx.x;
    long total = (long)BN * MID * HP * WP;
    if (idx >= total) return;
    int wp = (int)(idx % WP); long t = idx / WP;
    int hp = (int)(t % HP);   t /= HP;        // t = n*128 + c
    const float* base = in + t * (long)HO * WO + (long)(hp*2) * WO + wp*2;
    float m = -3.4e38f;
    #pragma unroll
    for (int a = 0; a < 3; a++)
        #pragma unroll
        for (int b2 = 0; b2 < 3; b2++)
            m = fmaxf(m, base[a*WO + b2]);
    out[idx] = m;
}

// ---------------- LRN (size=128 channel window) after BN+ReLU, fp64 --------
__global__ void k_lrn(int inbuf) {
    const float* in = getbuf(inbuf);
    int blk = blockIdx.x;
    int n = blk >> 4, hw = blk & 15;
    int c = threadIdx.x;
    __shared__ double sq[MID];
    float vf = in[(((long)n*MID + c) * 16) + hw];
    double v = fmax(fma((double)g_alpha[c], (double)vf, (double)g_beta[c]), 0.0);
    sq[c] = v * v;
    __syncthreads();
    int lo = c - 64 < 0 ? 0 : c - 64;
    int hi = c + 63 > 127 ? 127 : c + 63;
    double wsum = 0.0;
    for (int j = lo; j <= hi; j++) wsum += sq[j];
    double base = 1.0 + 1e-4 * (wsum / 128.0);
    g_feat[n*2048 + c*16 + hw] = (float)(v * pow(base, -0.75));
}

// ---------------- linear: reg = feat @ Wr^T + br  (fp64 accum) -------------
__global__ void k_linear(const float* __restrict__ Wr, const float* __restrict__ br) {
    int j = blockIdx.x % 7, n = blockIdx.x / 7;
    const float* f  = g_feat + n*2048;
    const float* wr = Wr + j*2048;
    double s = 0.0;
    for (int k = threadIdx.x; k < 2048; k += 32)
        s += (double)f[k] * (double)wr[k];
    #pragma unroll
    for (int o = 16; o > 0; o >>= 1)
        s += __shfl_down_sync(0xffffffffu, s, o);
    if (threadIdx.x == 0) g_reg[n*7 + j] = s + (double)br[j];
}

// ---------------- spectral normalize (sequential scan, fp64) + sigmoid -----
__global__ void k_spectral(const float* __restrict__ u0, const float* __restrict__ v0) {
    double u[2] = {(double)u0[0], (double)u0[1]};
    double v[3] = {(double)v0[0], (double)v0[1], (double)v0[2]};
    for (int n = 0; n < BN; n++) {
        double W[6];
        #pragma unroll
        for (int i = 0; i < 6; i++) W[i] = g_reg[n*7 + i];
        for (int it = 0; it < 4; it++) {
            double nv0 = W[0]*u[0] + W[3]*u[1];
            double nv1 = W[1]*u[0] + W[4]*u[1];
            double nv2 = W[2]*u[0] + W[5]*u[1];
            double nn = sqrt(nv0*nv0 + nv1*nv1 + nv2*nv2);
            nn = fmax(nn, 1e-12);
            v[0] = nv0/nn; v[1] = nv1/nn; v[2] = nv2/nn;
            double nu0 = W[0]*v[0] + W[1]*v[1] + W[2]*v[2];
            double nu1 = W[3]*v[0] + W[4]*v[1] + W[5]*v[2];
            nn = sqrt(nu0*nu0 + nu1*nu1);
            nn = fmax(nn, 1e-12);
            u[0] = nu0/nn; u[1] = nu1/nn;
        }
        double Wv0 = W[0]*v[0] + W[1]*v[1] + W[2]*v[2];
        double Wv1 = W[3]*v[0] + W[4]*v[1] + W[5]*v[2];
        double sigma = u[0]*Wv0 + u[1]*Wv1;
        #pragma unroll
        for (int i = 0; i < 6; i++) g_theta[n*6 + i] = W[i] / sigma;
        g_m[n] = 1.0 / (1.0 + exp(-g_reg[n*7 + 6]));
    }
}

// ---------------- affine grid + reflect bilinear sample + scale ------------
__device__ __forceinline__ double reflect_d(double x, double size) {
    double r = fabs(x + 0.5);
    r = fmod(r, 2.0 * size);
    if (r > size) r = 2.0 * size - r;
    r = r - 0.5;
    return fmin(fmax(r, 0.0), size - 1.0);
}

__global__ void k_sample(const float* __restrict__ x, float* __restrict__ out) {
    long idx = (long)blockIdx.x * 256 + threadIdx.x;    // over N*H*W
    if (idx >= (long)BN * HW0) return;
    int w = (int)(idx % WIN); long t = idx / WIN;
    int h = (int)(t % HIN);
    int n = (int)(t / HIN);

    const double* th = g_theta + n*6;
    double gx = (2.0*w + 1.0) / (double)WIN - 1.0;
    double gy = (2.0*h + 1.0) / (double)HIN - 1.0;
    double px = th[0]*gx + th[1]*gy + th[2];
    double py = th[3]*gx + th[4]*gy + th[5];

    double ix = reflect_d(((px + 1.0) * (double)WIN - 1.0) * 0.5, (double)WIN);
    double iy = reflect_d(((py + 1.0) * (double)HIN - 1.0) * 0.5, (double)HIN);

    double x0f = floor(ix), y0f = floor(iy);
    double wx = ix - x0f, wy = iy - y0f;
    int x0i = min(max((int)x0f, 0), WIN-1);
    int y0i = min(max((int)y0f, 0), HIN-1);
    int x1i = min(max((int)x0f + 1, 0), WIN-1);
    int y1i = min(max((int)y0f + 1, 0), HIN-1);

    double w00 = (1.0-wx)*(1.0-wy), w01 = wx*(1.0-wy);
    double w10 = (1.0-wx)*wy,       w11 = wx*wy;
    double mm = g_m[n];

    const float* xb = x   + (long)n*CIN*HW0;
    float*       ob = out + (long)n*CIN*HW0 + (long)h*WIN + w;
    int o00 = y0i*WIN + x0i, o01 = y0i*WIN + x1i;
    int o10 = y1i*WIN + x0i, o11 = y1i*WIN + x1i;
    for (int c = 0; c < CIN; c++) {
        const float* xc = xb + (long)c*HW0;
        double v = (double)xc[o00]*w00 + (double)xc[o01]*w01
                 + (double)xc[o10]*w10 + (double)xc[o11]*w11;
        ob[(long)c*HW0] = (float)(v * mm);
    }
}

// ---------------- host orchestration ----------------
extern "C" void kernel_launch(void* const* d_in, const int* in_sizes, int n_in,
                              void* d_out, int out_size) {
    const float* x       = (const float*)d_in[0];
    const float* conv0_w = (const float*)d_in[1];
    const float* conv0_b = (const float*)d_in[2];
    const float* convs_w = (const float*)d_in[3];
    const float* convs_b = (const float*)d_in[4];
    const float* bn_g    = (const float*)d_in[5];
    const float* bn_b    = (const float*)d_in[6];
    const float* Wr      = (const float*)d_in[7];
    const float* br      = (const float*)d_in[8];
    const float* u0      = (const float*)d_in[9];
    const float* v0      = (const float*)d_in[10];
    float* out = (float*)d_out;

    // conv0 (1x1) -> g_act0 (buf 0)
    k_conv0<<<(BN*HW0/4 + 255)/256, 256>>>(x, conv0_w, conv0_b);
    // bn0 stats on conv0 output
    k_bn<<<128, 256>>>(0, HW0, bn_g + 0*MID, bn_b + 0*MID);

    struct Stage { int inbuf, outbuf, HI, HO, HP; };
    const Stage st[5] = {
        {0, 2, 224, 222, 110},
        {2, 3, 110, 108,  53},
        {3, 2,  53,  51,  25},
        {2, 3,  25,  23,  11},
        {3, 2,  11,   9,   4},
    };

    for (int s = 0; s < 5; s++) {
        int HI = st[s].HI, HO = st[s].HO, HP = st[s].HP;
        dim3 grid((HO + 15)/16, (HO + 15)/16, BN * (MID/16));
        k_conv3<<<grid, 256>>>(st[s].inbuf,
                               convs_w + (size_t)s*MID*MID*9,
                               convs_b + s*MID,
                               HI, HI, HO, HO);
        long ptotal = (long)BN*MID*HP*HP;
        k_pool<<<(unsigned)((ptotal + 255)/256), 256>>>(st[s].outbuf, HO, HO, HP, HP);
        k_bn<<<128, 256>>>(st[s].outbuf, HP*HP, bn_g + (s+1)*MID, bn_b + (s+1)*MID);
    }

    // LRN on final pooled (buf 2 = g_pa, 16x128x4x4) with bn5 transform
    k_lrn<<<BN*16, MID>>>(2);
    // linear -> reg
    k_linear<<<BN*7, 32>>>(Wr, br);
    // spectral norm scan + m
    k_spectral<<<1, 1>>>(u0, v0);
    // sample
    k_sample<<<(unsigned)(((long)BN*HW0 + 255)/256), 256>>>(x, out);
}

// round 5
// speedup vs baseline: 1.2822x; 1.2822x over previous
#include <cuda_runtime.h>
#include <cuda_bf16.h>
#include <math.h>

// ---------------- problem constants ----------------
#define BN     16      // batch
#define CIN    16      // input channels
#define HIN    224
#define WIN    224
#define MID    128
#define HW0    (HIN*WIN)   // 50176

// ---------------- scratch (device globals; no allocation) ----------------
__device__ float g_act0[(size_t)BN*MID*224*224];   // conv0 raw output
__device__ float g_conv[(size_t)BN*MID*222*222];   // conv3x3 raw output (max size)
__device__ float g_pa  [(size_t)BN*MID*110*110];   // pooled ping
__device__ float g_pb  [(size_t)BN*MID*53*53];     // pooled pong
__device__ float  g_alpha[MID];
__device__ float  g_beta [MID];
__device__ float  g_feat[BN*2048];
__device__ double g_reg [BN*7];
__device__ double g_theta[BN*6];
__device__ double g_m[BN];

__device__ __forceinline__ float* getbuf(int s) {
    switch (s) {
        case 0: return g_act0;
        case 1: return g_conv;
        case 2: return g_pa;
        default: return g_pb;
    }
}

// ---------------- conv0: 1x1, 16 -> 128 ----------------
__global__ __launch_bounds__(256) void k_conv0(const float* __restrict__ x,
                                               const float* __restrict__ w,
                                               const float* __restrict__ b) {
    __shared__ float ws[MID*CIN];
    __shared__ float bs[MID];
    int tid = threadIdx.x;
    for (int i = tid; i < MID*CIN; i += 256) ws[i] = w[i];
    if (tid < MID) bs[tid] = b[tid];
    __syncthreads();

    long gid = (long)blockIdx.x * 256 + tid;             // pixel-group id
    int n  = (int)(gid / (HW0/4));
    int pg = (int)(gid % (HW0/4));
    int p  = pg * 4;

    const float* xp = x + (long)n*CIN*HW0 + p;
    float4 v[CIN];
    #pragma unroll
    for (int ci = 0; ci < CIN; ci++)
        v[ci] = *(const float4*)(xp + (long)ci*HW0);

    float* op = g_act0 + (long)n*MID*HW0 + p;
    for (int co = 0; co < MID; co++) {
        float4 a; a.x = a.y = a.z = a.w = bs[co];
        #pragma unroll
        for (int ci = 0; ci < CIN; ci++) {
            float wv = ws[co*CIN + ci];
            a.x = fmaf(v[ci].x, wv, a.x);
            a.y = fmaf(v[ci].y, wv, a.y);
            a.z = fmaf(v[ci].z, wv, a.z);
            a.w = fmaf(v[ci].w, wv, a.w);
        }
        *(float4*)(op + (long)co*HW0) = a;
    }
}

// ---------------- BN stats + finalize (fp64, deterministic) ----------------
__global__ void k_bn(int inbuf, int HWp, const float* __restrict__ g,
                     const float* __restrict__ b) {
    const float* p = getbuf(inbuf);
    int c = blockIdx.x;
    int tid = threadIdx.x;
    double s = 0.0, ss = 0.0;
    for (int n = 0; n < BN; n++) {
        const float* base = p + ((long)n*MID + c) * HWp;
        for (int i = tid; i < HWp; i += 256) {
            double v = (double)base[i];
            s += v; ss += v*v;
        }
    }
    __shared__ double sh[256], sh2[256];
    sh[tid] = s; sh2[tid] = ss;
    __syncthreads();
    for (int k = 128; k > 0; k >>= 1) {
        if (tid < k) { sh[tid] += sh[tid+k]; sh2[tid] += sh2[tid+k]; }
        __syncthreads();
    }
    if (tid == 0) {
        double M   = (double)BN * (double)HWp;
        double mu  = sh[0] / M;
        double var = sh2[0] / M - mu*mu;
        double a   = (double)g[c] / sqrt(var + 1e-5);
        g_alpha[c] = (float)a;
        g_beta[c]  = (float)((double)b[c] - mu*a);
    }
}

// ---------------- 3x3 valid conv, fused BN+ReLU on input ----------------
// block: 16 co x (16x16 px tile); thread: 1 co x 4x4 px
// fp32 accumulation within each 8-ci chunk; fp64 fold once per chunk.
// Double-buffered smem, register-staged prefetch, 1 barrier per chunk.
#define CI_CHUNK 8
#define NCHUNK   (MID/CI_CHUNK)      // 16
#define NIN_IT   11                  // ceil(8*18*18 / 256)
#define NW_IT    5                   // ceil(8*16*9 / 256)

__device__ __forceinline__ void ldrow6(float* r, const float* p) {
    float4 v = *(const float4*)p;
    float2 w = *(const float2*)(p + 4);
    r[0]=v.x; r[1]=v.y; r[2]=v.z; r[3]=v.w; r[4]=w.x; r[5]=w.y;
}

__device__ __forceinline__ void accrow(float* a, const float* ra, const float* rb,
                                       const float* rc, const float* wr) {
    #pragma unroll
    for (int j = 0; j < 4; j++) {
        float t = a[j];
        t = fmaf(ra[j  ], wr[0], t);
        t = fmaf(ra[j+1], wr[1], t);
        t = fmaf(ra[j+2], wr[2], t);
        t = fmaf(rb[j  ], wr[3], t);
        t = fmaf(rb[j+1], wr[4], t);
        t = fmaf(rb[j+2], wr[5], t);
        t = fmaf(rc[j  ], wr[6], t);
        t = fmaf(rc[j+1], wr[7], t);
        t = fmaf(rc[j+2], wr[8], t);
        a[j] = t;
    }
}

__global__ __launch_bounds__(256)
void k_conv3(int inbuf, const float* __restrict__ w, const float* __restrict__ bias,
             int HI, int WI, int HO, int WO) {
    __shared__ __align__(16) float s_in[2][CI_CHUNK][18][20];  // pitch 20 floats
    __shared__ __align__(16) float s_w [2][CI_CHUNK][16][12];

    const float* in = getbuf(inbuf);
    float* out = g_conv;

    int tid  = threadIdx.x;
    int co   = tid >> 4;                 // 0..15
    int slot = tid & 15;                 // 0..15
    int sx   = (slot & 3) * 4;
    int sy   = (slot >> 2) * 4;
    int ox0  = blockIdx.x * 16;
    int oy0  = blockIdx.y * 16;
    int n    = blockIdx.z >> 3;
    int co0  = (blockIdx.z & 7) << 4;
    int cog  = co0 + co;

    float stin[NIN_IT];
    float stw [NW_IT];

    auto load_chunk = [&](int ci0) {
        #pragma unroll
        for (int i = 0; i < NIN_IT; i++) {
            int idx = tid + 256*i;
            if (idx < CI_CHUNK*324) {
                int ci = idx / 324;
                int r  = (idx - ci*324) / 18;
                int cc = idx - ci*324 - r*18;
                int iy = oy0 + r, ix = ox0 + cc;
                float v = 0.f;
                if (iy < HI && ix < WI)
                    v = in[(((long)n*MID + ci0 + ci) * HI + iy) * WI + ix];
                stin[i] = fmaxf(fmaf(g_alpha[ci0+ci], v, g_beta[ci0+ci]), 0.f);
            }
        }
        #pragma unroll
        for (int i = 0; i < NW_IT; i++) {
            int idx = tid + 256*i;
            if (idx < CI_CHUNK*144) {
                int ci  = idx / 144;
                int rem = idx - ci*144;
                int col = rem / 9, k = rem - col*9;
                stw[i] = w[(((long)(co0+col))*MID + ci0 + ci)*9 + k];
            }
        }
    };
    auto store_chunk = [&](int buf) {
        #pragma unroll
        for (int i = 0; i < NIN_IT; i++) {
            int idx = tid + 256*i;
            if (idx < CI_CHUNK*324) {
                int ci = idx / 324;
                int r  = (idx - ci*324) / 18;
                int cc = idx - ci*324 - r*18;
                s_in[buf][ci][r][cc] = stin[i];
            }
        }
        #pragma unroll
        for (int i = 0; i < NW_IT; i++) {
            int idx = tid + 256*i;
            if (idx < CI_CHUNK*144) {
                int ci  = idx / 144;
                int rem = idx - ci*144;
                int col = rem / 9, k = rem - col*9;
                s_w[buf][ci][col][k] = stw[i];
            }
        }
    };

    double dacc[4][4];
    #pragma unroll
    for (int i = 0; i < 4; i++)
        #pragma unroll
        for (int j = 0; j < 4; j++) dacc[i][j] = 0.0;

    // prologue: chunk 0 into buffer 0
    load_chunk(0);
    store_chunk(0);

    for (int k = 0; k < NCHUNK; k++) {
        __syncthreads();                       // buf k&1 ready; buf (k+1)&1 free
        if (k + 1 < NCHUNK) load_chunk((k+1)*CI_CHUNK);   // LDGs in flight over compute

        int buf = k & 1;
        float acc[4][4];
        #pragma unroll
        for (int i = 0; i < 4; i++)
            #pragma unroll
            for (int j = 0; j < 4; j++) acc[i][j] = 0.f;

        #pragma unroll
        for (int ci = 0; ci < CI_CHUNK; ci++) {
            float wr[9];
            {   // vector weight load: pitch 12 floats -> 48B aligned
                const float* wp = &s_w[buf][ci][co][0];
                float4 w0 = *(const float4*)wp;
                float4 w1 = *(const float4*)(wp + 4);
                wr[0]=w0.x; wr[1]=w0.y; wr[2]=w0.z; wr[3]=w0.w;
                wr[4]=w1.x; wr[5]=w1.y; wr[6]=w1.z; wr[7]=w1.w;
                wr[8]=wp[8];
            }
            const float* base = &s_in[buf][ci][sy][sx];
            float r0[6], r1[6], r2[6];
            ldrow6(r0, base);
            ldrow6(r1, base + 20);
            ldrow6(r2, base + 40);
            accrow(acc[0], r0, r1, r2, wr);
            ldrow6(r0, base + 60);
            accrow(acc[1], r1, r2, r0, wr);
            ldrow6(r1, base + 80);
            accrow(acc[2], r2, r0, r1, wr);
            ldrow6(r2, base + 100);
            accrow(acc[3], r0, r1, r2, wr);
        }

        #pragma unroll
        for (int i = 0; i < 4; i++)
            #pragma unroll
            for (int j = 0; j < 4; j++) dacc[i][j] += (double)acc[i][j];

        if (k + 1 < NCHUNK) store_chunk((k+1) & 1);
    }

    double bv = (double)bias[cog];
    #pragma unroll
    for (int i = 0; i < 4; i++) {
        int oy = oy0 + sy + i;
        if (oy >= HO) continue;
        #pragma unroll
        for (int j = 0; j < 4; j++) {
            int ox = ox0 + sx + j;
            if (ox >= WO) continue;
            out[(((long)n*MID + cog) * HO + oy) * WO + ox] = (float)(dacc[i][j] + bv);
        }
    }
}

// ---------------- maxpool 3x3 stride 2 (valid) ----------------
__global__ void k_pool(int outbuf, int HO, int WO, int HP, int WP) {
    const float* in = g_conv;
    float* out = getbuf(outbuf);
    long idx = (long)blockIdx.x * 256 + threadIdx.x;
    long total = (long)BN * MID * HP * WP;
    if (idx >= total) return;
    int wp = (int)(idx % WP); long t = idx / WP;
    int hp = (int)(t % HP);   t /= HP;        // t = n*128 + c
    const float* base = in + t * (long)HO * WO + (long)(hp*2) * WO + wp*2;
    float m = -3.4e38f;
    #pragma unroll
    for (int a = 0; a < 3; a++)
        #pragma unroll
        for (int b2 = 0; b2 < 3; b2++)
            m = fmaxf(m, base[a*WO + b2]);
    out[idx] = m;
}

// ---------------- LRN (size=128 channel window) after BN+ReLU, fp64 --------
__global__ void k_lrn(int inbuf) {
    const float* in = getbuf(inbuf);
    int blk = blockIdx.x;
    int n = blk >> 4, hw = blk & 15;
    int c = threadIdx.x;
    __shared__ double sq[MID];
    float vf = in[(((long)n*MID + c) * 16) + hw];
    double v = fmax(fma((double)g_alpha[c], (double)vf, (double)g_beta[c]), 0.0);
    sq[c] = v * v;
    __syncthreads();
    int lo = c - 64 < 0 ? 0 : c - 64;
    int hi = c + 63 > 127 ? 127 : c + 63;
    double wsum = 0.0;
    for (int j = lo; j <= hi; j++) wsum += sq[j];
    double base = 1.0 + 1e-4 * (wsum / 128.0);
    g_feat[n*2048 + c*16 + hw] = (float)(v * pow(base, -0.75));
}

// ---------------- linear: reg = feat @ Wr^T + br  (fp64 accum) -------------
__global__ void k_linear(const float* __restrict__ Wr, const float* __restrict__ br) {
    int j = blockIdx.x % 7, n = blockIdx.x / 7;
    const float* f  = g_feat + n*2048;
    const float* wr = Wr + j*2048;
    double s = 0.0;
    for (int k = threadIdx.x; k < 2048; k += 32)
        s += (double)f[k] * (double)wr[k];
    #pragma unroll
    for (int o = 16; o > 0; o >>= 1)
        s += __shfl_down_sync(0xffffffffu, s, o);
    if (threadIdx.x == 0) g_reg[n*7 + j] = s + (double)br[j];
}

// ---------------- spectral normalize (sequential scan, fp64) + sigmoid -----
__global__ void k_spectral(const float* __restrict__ u0, const float* __restrict__ v0) {
    double u[2] = {(double)u0[0], (double)u0[1]};
    double v[3] = {(double)v0[0], (double)v0[1], (double)v0[2]};
    for (int n = 0; n < BN; n++) {
        double W[6];
        #pragma unroll
        for (int i = 0; i < 6; i++) W[i] = g_reg[n*7 + i];
        for (int it = 0; it < 4; it++) {
            double nv0 = W[0]*u[0] + W[3]*u[1];
            double nv1 = W[1]*u[0] + W[4]*u[1];
            double nv2 = W[2]*u[0] + W[5]*u[1];
            double nn = sqrt(nv0*nv0 + nv1*nv1 + nv2*nv2);
            nn = fmax(nn, 1e-12);
            v[0] = nv0/nn; v[1] = nv1/nn; v[2] = nv2/nn;
            double nu0 = W[0]*v[0] + W[1]*v[1] + W[2]*v[2];
            double nu1 = W[3]*v[0] + W[4]*v[1] + W[5]*v[2];
            nn = sqrt(nu0*nu0 + nu1*nu1);
            nn = fmax(nn, 1e-12);
            u[0] = nu0/nn; u[1] = nu1/nn;
        }
        double Wv0 = W[0]*v[0] + W[1]*v[1] + W[2]*v[2];
        double Wv1 = W[3]*v[0] + W[4]*v[1] + W[5]*v[2];
        double sigma = u[0]*Wv0 + u[1]*Wv1;
        #pragma unroll
        for (int i = 0; i < 6; i++) g_theta[n*6 + i] = W[i] / sigma;
        g_m[n] = 1.0 / (1.0 + exp(-g_reg[n*7 + 6]));
    }
}

// ---------------- affine grid + reflect bilinear sample + scale ------------
__device__ __forceinline__ double reflect_d(double x, double size) {
    double r = fabs(x + 0.5);
    r = fmod(r, 2.0 * size);
    if (r > size) r = 2.0 * size - r;
    r = r - 0.5;
    return fmin(fmax(r, 0.0), size - 1.0);
}

__global__ void k_sample(const float* __restrict__ x, float* __restrict__ out) {
    long idx = (long)blockIdx.x * 256 + threadIdx.x;    // over N*H*W
    if (idx >= (long)BN * HW0) return;
    int w = (int)(idx % WIN); long t = idx / WIN;
    int h = (int)(t % HIN);
    int n = (int)(t / HIN);

    const double* th = g_theta + n*6;
    double gx = (2.0*w + 1.0) / (double)WIN - 1.0;
    double gy = (2.0*h + 1.0) / (double)HIN - 1.0;
    double px = th[0]*gx + th[1]*gy + th[2];
    double py = th[3]*gx + th[4]*gy + th[5];

    double ix = reflect_d(((px + 1.0) * (double)WIN - 1.0) * 0.5, (double)WIN);
    double iy = reflect_d(((py + 1.0) * (double)HIN - 1.0) * 0.5, (double)HIN);

    double x0f = floor(ix), y0f = floor(iy);
    double wx = ix - x0f, wy = iy - y0f;
    int x0i = min(max((int)x0f, 0), WIN-1);
    int y0i = min(max((int)y0f, 0), HIN-1);
    int x1i = min(max((int)x0f + 1, 0), WIN-1);
    int y1i = min(max((int)y0f + 1, 0), HIN-1);

    double w00 = (1.0-wx)*(1.0-wy), w01 = wx*(1.0-wy);
    double w10 = (1.0-wx)*wy,       w11 = wx*wy;
    double mm = g_m[n];

    const float* xb = x   + (long)n*CIN*HW0;
    float*       ob = out + (long)n*CIN*HW0 + (long)h*WIN + w;
    int o00 = y0i*WIN + x0i, o01 = y0i*WIN + x1i;
    int o10 = y1i*WIN + x0i, o11 = y1i*WIN + x1i;
    for (int c = 0; c < CIN; c++) {
        const float* xc = xb + (long)c*HW0;
        double v = (double)xc[o00]*w00 + (double)xc[o01]*w01
                 + (double)xc[o10]*w10 + (double)xc[o11]*w11;
        ob[(long)c*HW0] = (float)(v * mm);
    }
}

// ---------------- host orchestration ----------------
extern "C" void kernel_launch(void* const* d_in, const int* in_sizes, int n_in,
                              void* d_out, int out_size) {
    const float* x       = (const float*)d_in[0];
    const float* conv0_w = (const float*)d_in[1];
    const float* conv0_b = (const float*)d_in[2];
    const float* convs_w = (const float*)d_in[3];
    const float* convs_b = (const float*)d_in[4];
    const float* bn_g    = (const float*)d_in[5];
    const float* bn_b    = (const float*)d_in[6];
    const float* Wr      = (const float*)d_in[7];
    const float* br      = (const float*)d_in[8];
    const float* u0      = (const float*)d_in[9];
    const float* v0      = (const float*)d_in[10];
    float* out = (float*)d_out;

    // conv0 (1x1) -> g_act0 (buf 0)
    k_conv0<<<(BN*HW0/4 + 255)/256, 256>>>(x, conv0_w, conv0_b);
    // bn0 stats on conv0 output
    k_bn<<<128, 256>>>(0, HW0, bn_g + 0*MID, bn_b + 0*MID);

    struct Stage { int inbuf, outbuf, HI, HO, HP; };
    const Stage st[5] = {
        {0, 2, 224, 222, 110},
        {2, 3, 110, 108,  53},
        {3, 2,  53,  51,  25},
        {2, 3,  25,  23,  11},
        {3, 2,  11,   9,   4},
    };

    for (int s = 0; s < 5; s++) {
        int HI = st[s].HI, HO = st[s].HO, HP = st[s].HP;
        dim3 grid((HO + 15)/16, (HO + 15)/16, BN * (MID/16));
        k_conv3<<<grid, 256>>>(st[s].inbuf,
                               convs_w + (size_t)s*MID*MID*9,
                               convs_b + s*MID,
                               HI, HI, HO, HO);
        long ptotal = (long)BN*MID*HP*HP;
        k_pool<<<(unsigned)((ptotal + 255)/256), 256>>>(st[s].outbuf, HO, HO, HP, HP);
        k_bn<<<128, 256>>>(st[s].outbuf, HP*HP, bn_g + (s+1)*MID, bn_b + (s+1)*MID);
    }

    // LRN on final pooled (buf 2 = g_pa, 16x128x4x4) with bn5 transform
    k_lrn<<<BN*16, MID>>>(2);
    // linear -> reg
    k_linear<<<BN*7, 32>>>(Wr, br);
    // spectral norm scan + m
    k_spectral<<<1, 1>>>(u0, v0);
    // sample
    k_sample<<<(unsigned)(((long)BN*HW0 + 255)/256), 256>>>(x, out);
}